// round 12
// baseline (speedup 1.0000x reference)
#include <cuda_runtime.h>

#define H 50
#define BTOT 2048
#define TLEN 1024
#define BTILE 16
#define NTH 200
#define XCH 16
#define GP 5    // hsh row: 5 float4 = 80B (odd*16B) -> at most 4-way store conflict

__device__ float g_h1[BTOT * H];

typedef unsigned long long u64;

__device__ __forceinline__ u64 ffma2n(u64 a, u64 b, u64 c) {
    u64 d; asm("fma.rn.f32x2 %0, %1, %2, %3;" : "=l"(d) : "l"(a), "l"(b), "l"(c)); return d;
}
__device__ __forceinline__ void ffma2(u64 &d, u64 a, u64 b) {
    asm("fma.rn.f32x2 %0, %1, %2, %0;" : "+l"(d) : "l"(a), "l"(b));
}
__device__ __forceinline__ u64 splat2(float x) {
    u64 r; asm("mov.b64 %0, {%1, %1};" : "=l"(r) : "f"(x)); return r;
}
__device__ __forceinline__ void unpack2(u64 v, float &lo, float &hi) {
    asm("mov.b64 {%0, %1}, %2;" : "=f"(lo), "=f"(hi) : "l"(v));
}

// Single-MUFU activations.
__device__ __forceinline__ float tanh_f(float x) {
    float y; asm("tanh.approx.f32 %0, %1;" : "=f"(y) : "f"(x)); return y;
}
__device__ __forceinline__ float sigf(float x) {
    return fmaf(0.5f, tanh_f(0.5f * x), 0.5f);
}

// Empty kernel: shifts ncu's -s 5 -c 1 capture window so launch #6 = lstm1.
__global__ void profile_pad_kernel() {}

// Layer 1: persistent recurrence. 200 threads = 4 batch-groups x 50 hidden.
// Accumulators packed across BATCH pairs: aG01=(pre_G[b0],pre_G[b1]) etc.
//  - h operand: natural (h0,h1)/(h2,h3) pairs -> broadcast LDS.64, no splats.
//  - weights: one LDS.128 (Wi,Wf,Wg,Wo) + 4 register splats per k.
// Inner k: 1 LDS.128 + 2 LDS.64 + 4 MOV + 8 FFMA2 = 15 instr.
__global__ void __launch_bounds__(NTH) lstm1_kernel(
    const float* __restrict__ x,
    const float* __restrict__ Wih,
    const float* __restrict__ Whh,
    const float* __restrict__ bih,
    const float* __restrict__ bhh)
{
    __shared__ __align__(16) float4 Wq[H][H];        // [k][j] = (Wi,Wf,Wg,Wo)[j][k]  40000B
    __shared__ __align__(16) float4 hsh[2][H][GP];   // [buf][k][group] = (h0..h3)     8000B
    __shared__ __align__(16) float  xsh[XCH][16];    // x chunk                        1024B

    const int tid = threadIdx.x;
    const int bg = tid / H;          // 0..3
    const int j  = tid - bg * H;     // 0..49, all threads active
    const int bbase = blockIdx.x * BTILE;

    // Prepack Whh gate quads: Wq[k][j] = 4 gate rows at column k
    for (int i = tid; i < H * H; i += NTH) {
        int k = i / H, jj = i - k * H;
        Wq[k][jj] = make_float4(Whh[jj * H + k],
                                Whh[(H + jj) * H + k],
                                Whh[(2 * H + jj) * H + k],
                                Whh[(3 * H + jj) * H + k]);
    }
    for (int i = tid; i < 2 * H * GP; i += NTH)
        ((float4*)hsh)[i] = make_float4(0.f, 0.f, 0.f, 0.f);

    // Per-thread splatted constants (same value for both batches of a pair)
    const u64 bI = splat2(bih[j]         + bhh[j]);
    const u64 bF = splat2(bih[H + j]     + bhh[H + j]);
    const u64 bG = splat2(bih[2 * H + j] + bhh[2 * H + j]);
    const u64 bO = splat2(bih[3 * H + j] + bhh[3 * H + j]);
    const u64 wiI = splat2(Wih[j]);
    const u64 wiF = splat2(Wih[H + j]);
    const u64 wiG = splat2(Wih[2 * H + j]);
    const u64 wiO = splat2(Wih[3 * H + j]);

    float c[4]  = {0.f, 0.f, 0.f, 0.f};
    float hv[4] = {0.f, 0.f, 0.f, 0.f};

    __syncthreads();

    for (int t = 0; t < TLEN; t++) {
        if ((t & (XCH - 1)) == 0) {
            // previous end-of-step barrier guarantees old xsh reads are done
            for (int i = tid; i < XCH * BTILE; i += NTH) {
                int tc = i >> 4, bl = i & 15;
                xsh[tc][bl] = x[(bbase + bl) * TLEN + t + tc];
            }
            __syncthreads();
        }
        const int buf = t & 1;

        // x pairs for this group's 4 batches
        const u64* xp = (const u64*)&xsh[t & (XCH - 1)][bg * 4];
        const u64 x01 = xp[0], x23 = xp[1];

        u64 aI01 = ffma2n(x01, wiI, bI), aI23 = ffma2n(x23, wiI, bI);
        u64 aF01 = ffma2n(x01, wiF, bF), aF23 = ffma2n(x23, wiF, bF);
        u64 aG01 = ffma2n(x01, wiG, bG), aG23 = ffma2n(x23, wiG, bG);
        u64 aO01 = ffma2n(x01, wiO, bO), aO23 = ffma2n(x23, wiO, bO);

#pragma unroll
        for (int k = 0; k < H; k++) {
            const float4 w = Wq[k][j];                       // LDS.128
            const u64* hp = (const u64*)&hsh[buf][k][bg];    // broadcast
            const u64 h01 = hp[0], h23 = hp[1];
            const u64 wI = splat2(w.x), wF = splat2(w.y);
            const u64 wG = splat2(w.z), wO = splat2(w.w);
            ffma2(aI01, h01, wI); ffma2(aI23, h23, wI);
            ffma2(aF01, h01, wF); ffma2(aF23, h23, wF);
            ffma2(aG01, h01, wG); ffma2(aG23, h23, wG);
            ffma2(aO01, h01, wO); ffma2(aO23, h23, wO);
        }

        float ip[4], fp[4], gp[4], op[4];
        unpack2(aI01, ip[0], ip[1]); unpack2(aI23, ip[2], ip[3]);
        unpack2(aF01, fp[0], fp[1]); unpack2(aF23, fp[2], fp[3]);
        unpack2(aG01, gp[0], gp[1]); unpack2(aG23, gp[2], gp[3]);
        unpack2(aO01, op[0], op[1]); unpack2(aO23, op[2], op[3]);
#pragma unroll
        for (int r = 0; r < 4; r++) {
            const float ig = sigf(ip[r]);
            const float fg = sigf(fp[r]);
            const float gg = tanh_f(gp[r]);
            const float og = sigf(op[r]);
            c[r]  = fmaf(fg, c[r], ig * gg);
            hv[r] = og * tanh_f(c[r]);
        }
        hsh[buf ^ 1][j][bg] = make_float4(hv[0], hv[1], hv[2], hv[3]);
        __syncthreads();
    }

#pragma unroll
    for (int r = 0; r < 4; r++)
        g_h1[(bbase + bg * 4 + r) * H + j] = hv[r];
}

#define NTH2 256

__global__ void __launch_bounds__(NTH2) lstm2_fc_kernel(
    const float* __restrict__ W2ih,
    const float* __restrict__ b2ih,
    const float* __restrict__ b2hh,
    const float* __restrict__ fcW,
    const float* __restrict__ fcb,
    float* __restrict__ out)
{
    __shared__ __align__(16) float Wsh[H][4 * H];
    __shared__ __align__(16) float h1sh[H][BTILE];
    __shared__ float h2sh[BTILE][H];

    const int tid = threadIdx.x;
    const int j = tid & 63;
    const int bg = tid >> 6;
    const int bbase = blockIdx.x * BTILE;
    const int bloc = bg * 4;

    for (int i = tid; i < 4 * H * H; i += NTH2) {
        int g = i / H, k = i - g * H;
        Wsh[k][g] = W2ih[i];
    }
    for (int i = tid; i < H * BTILE; i += NTH2) {
        int k = i >> 4, bl = i & 15;
        h1sh[k][bl] = g_h1[(bbase + bl) * H + k];
    }
    __syncthreads();

    if (j < H) {
        const float bias0 = b2ih[j]         + b2hh[j];
        const float bias2 = b2ih[2 * H + j] + b2hh[2 * H + j];
        const float bias3 = b2ih[3 * H + j] + b2hh[3 * H + j];
        float a0[4], a2[4], a3[4];
#pragma unroll
        for (int r = 0; r < 4; r++) { a0[r] = bias0; a2[r] = bias2; a3[r] = bias3; }
#pragma unroll
        for (int k = 0; k < H; k++) {
            const float w0 = Wsh[k][j];
            const float w2 = Wsh[k][2 * H + j];
            const float w3 = Wsh[k][3 * H + j];
            const float4 h4 = *(const float4*)&h1sh[k][bloc];
            const float hr[4] = {h4.x, h4.y, h4.z, h4.w};
#pragma unroll
            for (int r = 0; r < 4; r++) {
                a0[r] = fmaf(hr[r], w0, a0[r]);
                a2[r] = fmaf(hr[r], w2, a2[r]);
                a3[r] = fmaf(hr[r], w3, a3[r]);
            }
        }
#pragma unroll
        for (int r = 0; r < 4; r++) {
            const float ig = sigf(a0[r]);           // f-gate unused: c0 = 0
            const float gg = tanh_f(a2[r]);
            const float og = sigf(a3[r]);
            const float cc = ig * gg;
            h2sh[bloc + r][j] = og * tanh_f(cc);
        }
    }
    __syncthreads();

    if (tid < BTILE) {
        float s = fcb[0];
#pragma unroll
        for (int k = 0; k < H; k++)
            s = fmaf(h2sh[tid][k], fcW[k], s);
        out[bbase + tid] = s;
    }
}

extern "C" void kernel_launch(void* const* d_in, const int* in_sizes, int n_in,
                              void* d_out, int out_size)
{
    const float* x     = (const float*)d_in[0];
    const float* w1ih  = (const float*)d_in[1];
    const float* w1hh  = (const float*)d_in[2];
    const float* b1ih  = (const float*)d_in[3];
    const float* b1hh  = (const float*)d_in[4];
    const float* w2ih  = (const float*)d_in[5];
    // d_in[6] = lstm2_Whh: unused (layer-2 initial state is zero)
    const float* b2ih  = (const float*)d_in[7];
    const float* b2hh  = (const float*)d_in[8];
    const float* fcW   = (const float*)d_in[9];
    const float* fcb   = (const float*)d_in[10];
    float* out = (float*)d_out;

    lstm1_kernel<<<BTOT / BTILE, NTH>>>(x, w1ih, w1hh, b1ih, b1hh);
    lstm2_fc_kernel<<<BTOT / BTILE, NTH2>>>(w2ih, b2ih, b2hh, fcW, fcb, out);

    // 3 empty pad launches: sequence per call = (L1, L2, D, D, D), so ncu's
    // "-s 5 -c 1" capture (6th launch) lands on lstm1_kernel next round.
    profile_pad_kernel<<<1, 32>>>();
    profile_pad_kernel<<<1, 32>>>();
    profile_pad_kernel<<<1, 32>>>();
}

// round 13
// speedup vs baseline: 1.0162x; 1.0162x over previous
#include <cuda_runtime.h>

#define H 50
#define BTOT 2048
#define TLEN 1024
#define NBAT 16          // batches per block
#define NTH 128          // 4 warps, 1 per SMSP; active: j<50 (100 threads)
#define XCH 16
#define GP 20            // hsh row: 20 floats = 80B (odd*16B) -> <=4-way conflicts

typedef unsigned long long u64;

__device__ __forceinline__ u64 ffma2n(u64 a, u64 b, u64 c) {
    u64 d; asm("fma.rn.f32x2 %0, %1, %2, %3;" : "=l"(d) : "l"(a), "l"(b), "l"(c)); return d;
}
__device__ __forceinline__ void ffma2(u64 &d, u64 a, u64 b) {
    asm("fma.rn.f32x2 %0, %1, %2, %0;" : "+l"(d) : "l"(a), "l"(b));
}
__device__ __forceinline__ u64 splat2(float x) {
    u64 r; asm("mov.b64 %0, {%1, %1};" : "=l"(r) : "f"(x)); return r;
}
__device__ __forceinline__ void unpack2(u64 v, float &lo, float &hi) {
    asm("mov.b64 {%0, %1}, %2;" : "=f"(lo), "=f"(hi) : "l"(v));
}
__device__ __forceinline__ float tanh_f(float x) {
    float y; asm("tanh.approx.f32 %0, %1;" : "=f"(y) : "f"(x)); return y;
}
__device__ __forceinline__ float sigf(float x) {
    return fmaf(0.5f, tanh_f(0.5f * x), 0.5f);
}

// Fully fused: lstm1 recurrence (1024 steps) + lstm2 single cell + FC, one kernel.
// Block owns 16 batches. Thread (j = tid&63 [<50 active], bg = tid>>6) computes
// all 4 gates of hidden unit j for 8 batches (slots bg*8 .. bg*8+7).
// Batch-pair-packed FFMA2: one LDS.128 weight quad feeds 16 FFMA2 (128 flops/16B).
__global__ void __launch_bounds__(NTH) fused_lstm_kernel(
    const float* __restrict__ x,
    const float* __restrict__ Wih,
    const float* __restrict__ Whh,
    const float* __restrict__ bih,
    const float* __restrict__ bhh,
    const float* __restrict__ W2ih,
    const float* __restrict__ b2ih,
    const float* __restrict__ b2hh,
    const float* __restrict__ fcW,
    const float* __restrict__ fcb,
    float* __restrict__ out)
{
    __shared__ __align__(16) float4 Wq[H][H];       // [k][j] = (Wi,Wf,Wg,Wo)[j][k]  40000B
    __shared__ __align__(16) float  hsh[2][H][GP];  // double-buffered h              8000B
    __shared__ __align__(16) float  xsh[XCH][NBAT]; // x chunk                        1024B

    const int tid = threadIdx.x;
    const int bg  = tid >> 6;        // 0..1
    const int j   = tid & 63;        // active if < 50
    const bool act = j < H;
    const int bbase = blockIdx.x * NBAT;
    const int sl = bg * 8;           // batch slot base (0 or 8)

    // Prepack Whh gate quads: Wq[k][jj] = 4 gate rows at column k
    for (int i = tid; i < H * H; i += NTH) {
        int k = i / H, jj = i - k * H;
        Wq[k][jj] = make_float4(Whh[jj * H + k],
                                Whh[(H + jj) * H + k],
                                Whh[(2 * H + jj) * H + k],
                                Whh[(3 * H + jj) * H + k]);
    }
    for (int i = tid; i < 2 * H * GP; i += NTH)
        (&hsh[0][0][0])[i] = 0.0f;

    u64 bI = 0, bF = 0, bG = 0, bO = 0, wiI = 0, wiF = 0, wiG = 0, wiO = 0;
    if (act) {
        bI = splat2(bih[j]         + bhh[j]);
        bF = splat2(bih[H + j]     + bhh[H + j]);
        bG = splat2(bih[2 * H + j] + bhh[2 * H + j]);
        bO = splat2(bih[3 * H + j] + bhh[3 * H + j]);
        wiI = splat2(Wih[j]);
        wiF = splat2(Wih[H + j]);
        wiG = splat2(Wih[2 * H + j]);
        wiO = splat2(Wih[3 * H + j]);
    }

    float c[8]  = {0.f, 0.f, 0.f, 0.f, 0.f, 0.f, 0.f, 0.f};
    float hv[8] = {0.f, 0.f, 0.f, 0.f, 0.f, 0.f, 0.f, 0.f};

    __syncthreads();

    for (int t = 0; t < TLEN; t++) {
        if ((t & (XCH - 1)) == 0) {
            // previous end-of-step barrier guarantees old xsh reads are done
            for (int i = tid; i < XCH * NBAT; i += NTH) {
                int tc = i >> 4, bl = i & 15;
                xsh[tc][bl] = x[(bbase + bl) * TLEN + t + tc];
            }
            __syncthreads();
        }
        const int buf = t & 1;

        if (act) {
            const u64* xp = (const u64*)&xsh[t & (XCH - 1)][sl];
            const u64 x01 = xp[0], x23 = xp[1], x45 = xp[2], x67 = xp[3];

            u64 aI[4], aF[4], aG[4], aO[4];
            aI[0] = ffma2n(x01, wiI, bI); aI[1] = ffma2n(x23, wiI, bI);
            aI[2] = ffma2n(x45, wiI, bI); aI[3] = ffma2n(x67, wiI, bI);
            aF[0] = ffma2n(x01, wiF, bF); aF[1] = ffma2n(x23, wiF, bF);
            aF[2] = ffma2n(x45, wiF, bF); aF[3] = ffma2n(x67, wiF, bF);
            aG[0] = ffma2n(x01, wiG, bG); aG[1] = ffma2n(x23, wiG, bG);
            aG[2] = ffma2n(x45, wiG, bG); aG[3] = ffma2n(x67, wiG, bG);
            aO[0] = ffma2n(x01, wiO, bO); aO[1] = ffma2n(x23, wiO, bO);
            aO[2] = ffma2n(x45, wiO, bO); aO[3] = ffma2n(x67, wiO, bO);

#pragma unroll 10
            for (int k = 0; k < H; k++) {
                const float4 w = Wq[k][j];                      // LDS.128
                const u64* hp = (const u64*)&hsh[buf][k][sl];   // broadcast LDS.64 x4
                const u64 h01 = hp[0], h23 = hp[1], h45 = hp[2], h67 = hp[3];
                const u64 wI = splat2(w.x), wF = splat2(w.y);
                const u64 wG = splat2(w.z), wO = splat2(w.w);
                ffma2(aI[0], h01, wI); ffma2(aI[1], h23, wI);
                ffma2(aI[2], h45, wI); ffma2(aI[3], h67, wI);
                ffma2(aF[0], h01, wF); ffma2(aF[1], h23, wF);
                ffma2(aF[2], h45, wF); ffma2(aF[3], h67, wF);
                ffma2(aG[0], h01, wG); ffma2(aG[1], h23, wG);
                ffma2(aG[2], h45, wG); ffma2(aG[3], h67, wG);
                ffma2(aO[0], h01, wO); ffma2(aO[1], h23, wO);
                ffma2(aO[2], h45, wO); ffma2(aO[3], h67, wO);
            }

            float ip[8], fp[8], gp[8], op[8];
#pragma unroll
            for (int r = 0; r < 4; r++) {
                unpack2(aI[r], ip[2 * r], ip[2 * r + 1]);
                unpack2(aF[r], fp[2 * r], fp[2 * r + 1]);
                unpack2(aG[r], gp[2 * r], gp[2 * r + 1]);
                unpack2(aO[r], op[2 * r], op[2 * r + 1]);
            }
#pragma unroll
            for (int r = 0; r < 8; r++) {
                const float ig = sigf(ip[r]);
                const float fg = sigf(fp[r]);
                const float gg = tanh_f(gp[r]);
                const float og = sigf(op[r]);
                c[r]  = fmaf(fg, c[r], ig * gg);
                hv[r] = og * tanh_f(c[r]);
            }
            float* hd = &hsh[buf ^ 1][j][sl];
            *(float4*)hd       = make_float4(hv[0], hv[1], hv[2], hv[3]);
            *(float4*)(hd + 4) = make_float4(hv[4], hv[5], hv[6], hv[7]);
        }
        __syncthreads();
    }
    // Final h1 lives in hsh buffer 0 (t=1023: buf=1, wrote buf^1=0).

    // ---- lstm2 single cell (zero initial state) + FC, fused ----
    // Reload Wq with W2ih gate quads (Whh2 unused: h0 = 0).
    for (int i = tid; i < H * H; i += NTH) {
        int k = i / H, jj = i - k * H;
        Wq[k][jj] = make_float4(W2ih[jj * H + k],
                                W2ih[(H + jj) * H + k],
                                W2ih[(2 * H + jj) * H + k],
                                W2ih[(3 * H + jj) * H + k]);
    }
    __syncthreads();

    float* h2s = &hsh[1][0][0];   // buffer 1 is free; layout [j][slot] (GP stride)

    if (act) {
        const u64 cI = splat2(b2ih[j]         + b2hh[j]);
        const u64 cG = splat2(b2ih[2 * H + j] + b2hh[2 * H + j]);
        const u64 cO = splat2(b2ih[3 * H + j] + b2hh[3 * H + j]);
        u64 aI[4] = {cI, cI, cI, cI};
        u64 aG[4] = {cG, cG, cG, cG};
        u64 aO[4] = {cO, cO, cO, cO};   // f-gate skipped: c0 = 0
#pragma unroll 10
        for (int k = 0; k < H; k++) {
            const float4 w = Wq[k][j];
            const u64* hp = (const u64*)&hsh[0][k][sl];
            const u64 h01 = hp[0], h23 = hp[1], h45 = hp[2], h67 = hp[3];
            const u64 wI = splat2(w.x), wG = splat2(w.z), wO = splat2(w.w);
            ffma2(aI[0], h01, wI); ffma2(aI[1], h23, wI);
            ffma2(aI[2], h45, wI); ffma2(aI[3], h67, wI);
            ffma2(aG[0], h01, wG); ffma2(aG[1], h23, wG);
            ffma2(aG[2], h45, wG); ffma2(aG[3], h67, wG);
            ffma2(aO[0], h01, wO); ffma2(aO[1], h23, wO);
            ffma2(aO[2], h45, wO); ffma2(aO[3], h67, wO);
        }
        float ip[8], gp[8], op[8];
#pragma unroll
        for (int r = 0; r < 4; r++) {
            unpack2(aI[r], ip[2 * r], ip[2 * r + 1]);
            unpack2(aG[r], gp[2 * r], gp[2 * r + 1]);
            unpack2(aO[r], op[2 * r], op[2 * r + 1]);
        }
        float h2[8];
#pragma unroll
        for (int r = 0; r < 8; r++) {
            const float ig = sigf(ip[r]);
            const float gg = tanh_f(gp[r]);
            const float og = sigf(op[r]);
            h2[r] = og * tanh_f(ig * gg);   // c = i*g (f*c0 = 0)
        }
        float* hd = &h2s[j * GP + sl];
        *(float4*)hd       = make_float4(h2[0], h2[1], h2[2], h2[3]);
        *(float4*)(hd + 4) = make_float4(h2[4], h2[5], h2[6], h2[7]);
    }
    __syncthreads();

    if (tid < NBAT) {
        float s = fcb[0];
#pragma unroll 10
        for (int k = 0; k < H; k++)
            s = fmaf(h2s[k * GP + tid], __ldg(&fcW[k]), s);
        out[bbase + tid] = s;
    }
}

extern "C" void kernel_launch(void* const* d_in, const int* in_sizes, int n_in,
                              void* d_out, int out_size)
{
    const float* x     = (const float*)d_in[0];
    const float* w1ih  = (const float*)d_in[1];
    const float* w1hh  = (const float*)d_in[2];
    const float* b1ih  = (const float*)d_in[3];
    const float* b1hh  = (const float*)d_in[4];
    const float* w2ih  = (const float*)d_in[5];
    // d_in[6] = lstm2_Whh: unused (layer-2 initial state is zero)
    const float* b2ih  = (const float*)d_in[7];
    const float* b2hh  = (const float*)d_in[8];
    const float* fcW   = (const float*)d_in[9];
    const float* fcb   = (const float*)d_in[10];
    float* out = (float*)d_out;

    fused_lstm_kernel<<<BTOT / NBAT, NTH>>>(
        x, w1ih, w1hh, b1ih, b1hh, w2ih, b2ih, b2hh, fcW, fcb, out);
}